// round 7
// baseline (speedup 1.0000x reference)
#include <cuda_runtime.h>
#include <cstdint>

// out[b, q, dv] = (1/SK) * sum_k value[b, k, dv]
// (q and k are the same broadcast scalar -> all logits equal -> softmax uniform
//  -> output = mean of value over SK, independent of query and q_param.)
//
// One cluster (8 CTAs) per batch. Each CTA reduces 256 rows, shares its 512B
// partial via DSMEM after a HW cluster barrier, then writes 256 output rows.

#define B   16
#define SQ  2048
#define SK  2048
#define DV  128
#define CPC 8                    // CTAs per cluster (= per batch)
#define RPC (SK / CPC)           // 256 rows reduced per CTA
#define THREADS 512

__device__ __forceinline__ uint32_t smem_u32(const void* p) {
    uint32_t a;
    asm("{ .reg .u64 t; cvta.to.shared.u64 t, %1; cvt.u32.u64 %0, t; }"
        : "=r"(a) : "l"(p));
    return a;
}

__global__ void __launch_bounds__(THREADS, 1) __cluster_dims__(CPC, 1, 1)
fused_kernel(const float4* __restrict__ value, float4* __restrict__ out) {
    const int b   = blockIdx.y;
    const int c   = blockIdx.x;          // cluster rank 0..7
    const int tid = threadIdx.x;
    const int dv4 = tid & 31;            // float4 column 0..31
    const int rg  = tid >> 5;            // row group 0..15

    __shared__ float4 tmp[THREADS];
    __shared__ __align__(16) float4 my_part[32];   // this CTA's 512B partial

    // ---- Phase A: reduce rows [c*256, c*256+256), 16 rows per thread ----
    const float4* base = value + ((size_t)b * SK + c * RPC + rg) * (DV / 4) + dv4;
    float4 s = make_float4(0.f, 0.f, 0.f, 0.f);
    #pragma unroll
    for (int k = 0; k < RPC / 16; ++k) {
        float4 v = base[(size_t)k * 16 * (DV / 4)];
        s.x += v.x; s.y += v.y; s.z += v.z; s.w += v.w;
    }
    tmp[tid] = s;
    __syncthreads();

    if (tid < 32) {
        float4 a = tmp[tid];
        #pragma unroll
        for (int g = 1; g < 16; ++g) {
            float4 v = tmp[g * 32 + tid];
            a.x += v.x; a.y += v.y; a.z += v.z; a.w += v.w;
        }
        my_part[tid] = a;
    }
    __syncthreads();

    // ---- HW cluster barrier: publish my_part, then read peers via DSMEM ----
    asm volatile("barrier.cluster.arrive.aligned;" ::: "memory");
    asm volatile("barrier.cluster.wait.aligned;"   ::: "memory");

    __shared__ float4 fin[32];
    if (tid < 32) {
        const uint32_t la = smem_u32(&my_part[tid]);
        float4 a = make_float4(0.f, 0.f, 0.f, 0.f);
        #pragma unroll
        for (int r = 0; r < CPC; ++r) {
            uint32_t ra;
            asm("mapa.shared::cluster.u32 %0, %1, %2;" : "=r"(ra) : "r"(la), "r"(r));
            float4 v;
            asm volatile("ld.shared::cluster.v4.f32 {%0,%1,%2,%3}, [%4];"
                         : "=f"(v.x), "=f"(v.y), "=f"(v.z), "=f"(v.w) : "r"(ra));
            a.x += v.x; a.y += v.y; a.z += v.z; a.w += v.w;
        }
        const float inv = 1.0f / (float)SK;
        a.x *= inv; a.y *= inv; a.z *= inv; a.w *= inv;
        fin[tid] = a;
    }
    __syncthreads();

    // ---- Phase C: write 256 output rows [c*256, c*256+256) ----
    {
        const float4 v = fin[dv4];
        float4* o = out + ((size_t)b * SQ + c * RPC + rg) * (DV / 4) + dv4;
        #pragma unroll
        for (int i = 0; i < RPC / 16; ++i) {
            o[(size_t)i * 16 * (DV / 4)] = v;
        }
    }

    // ---- Keep smem alive until all peers finished their DSMEM reads ----
    asm volatile("barrier.cluster.arrive.aligned;" ::: "memory");
    asm volatile("barrier.cluster.wait.aligned;"   ::: "memory");
}

extern "C" void kernel_launch(void* const* d_in, const int* in_sizes, int n_in,
                              void* d_out, int out_size) {
    // inputs: query[B,SQ,D], key[B,SK,D], value[B,SK,DV], q_param[1,1]
    const float4* value = (const float4*)d_in[2];
    float4* out = (float4*)d_out;

    dim3 grid(CPC, B);
    fused_kernel<<<grid, THREADS>>>(value, out);
}

// round 9
// speedup vs baseline: 1.3219x; 1.3219x over previous
#include <cuda_runtime.h>

// out[b, q, dv] = (1/SK) * sum_k value[b, k, dv]
// (q and k are the same broadcast scalar -> all logits equal -> softmax uniform
//  -> output = mean of value over SK, independent of query and q_param.)
//
// Two kernels chained with PDL (programmatic dependent launch): broadcast
// CTAs launch while reduce is still running and wait in
// cudaGridDependencySynchronize() instead of a full graph-edge drain.

#define B   16
#define SQ  2048
#define SK  2048
#define DV  128
#define SPB 8                    // splits (CTAs) per batch in reduce
#define RPC (SK / SPB)           // 256 rows per reduce CTA

__device__ float4 g_part[B * SPB * 32];   // per-(b,split) partial row (512B each)

// grid (B, SPB) = 128 CTAs, block 256. Each CTA reduces 256 rows.
// tid: dv4 = float4 column, rg = one of 8 row groups (32 rows each, stride 8).
__global__ void __launch_bounds__(256)
reduce_kernel(const float4* __restrict__ value) {
    const int b   = blockIdx.x;
    const int sp  = blockIdx.y;
    const int tid = threadIdx.x;
    const int dv4 = tid & 31;
    const int rg  = tid >> 5;

    const float4* base = value + ((size_t)b * SK + sp * RPC + rg) * (DV / 4) + dv4;
    float4 s = make_float4(0.f, 0.f, 0.f, 0.f);
    #pragma unroll
    for (int k = 0; k < RPC / 8; ++k) {
        float4 v = base[(size_t)k * 8 * (DV / 4)];
        s.x += v.x; s.y += v.y; s.z += v.z; s.w += v.w;
    }

    __shared__ float4 tmp[256];
    tmp[tid] = s;
    __syncthreads();

    if (tid < 32) {
        float4 a = tmp[tid];
        #pragma unroll
        for (int g = 1; g < 8; ++g) {
            float4 v = tmp[g * 32 + tid];
            a.x += v.x; a.y += v.y; a.z += v.z; a.w += v.w;
        }
        g_part[(b * SPB + sp) * 32 + tid] = a;
    }
}

// grid (64, B) = 1024 CTAs, block 256. Each CTA writes 32 rows of batch b.
// Prologue overlaps with reduce; cudaGridDependencySynchronize() provides the
// dependency + memory visibility on g_part.
__global__ void __launch_bounds__(256)
broadcast_kernel(float4* __restrict__ out) {
    const int b     = blockIdx.y;
    const int chunk = blockIdx.x;         // 32-row chunk
    const int tid   = threadIdx.x;
    const int dv4   = tid & 31;
    const int rg    = tid >> 5;           // 0..7

    __shared__ float4 tmp[256];
    __shared__ float4 fin[32];

    float4* o = out + ((size_t)b * SQ + chunk * 32 + rg) * (DV / 4) + dv4;

    cudaGridDependencySynchronize();

    // combine: one global load per thread (8 splits x 32 columns)
    tmp[tid] = g_part[(b * SPB + rg) * 32 + dv4];
    __syncthreads();

    if (tid < 32) {
        const float inv = 1.0f / (float)SK;
        float4 a = tmp[tid];
        #pragma unroll
        for (int g = 1; g < 8; ++g) {
            float4 v = tmp[g * 32 + tid];
            a.x += v.x; a.y += v.y; a.z += v.z; a.w += v.w;
        }
        a.x *= inv; a.y *= inv; a.z *= inv; a.w *= inv;
        fin[tid] = a;
    }
    __syncthreads();

    const float4 v = fin[dv4];
    #pragma unroll
    for (int i = 0; i < 4; ++i) {
        o[(size_t)i * 8 * (DV / 4)] = v;
    }
}

extern "C" void kernel_launch(void* const* d_in, const int* in_sizes, int n_in,
                              void* d_out, int out_size) {
    // inputs: query[B,SQ,D], key[B,SK,D], value[B,SK,DV], q_param[1,1]
    const float4* value = (const float4*)d_in[2];
    float4* out = (float4*)d_out;

    {
        dim3 rgrid(B, SPB);
        reduce_kernel<<<rgrid, 256>>>(value);
    }

    {
        cudaLaunchConfig_t cfg = {};
        cfg.gridDim  = dim3(64, B, 1);
        cfg.blockDim = dim3(256, 1, 1);
        cfg.dynamicSmemBytes = 0;
        cfg.stream = 0;

        cudaLaunchAttribute attr[1];
        attr[0].id = cudaLaunchAttributeProgrammaticStreamSerialization;
        attr[0].val.programmaticStreamSerializationAllowed = 1;
        cfg.attrs = attr;
        cfg.numAttrs = 1;

        cudaLaunchKernelEx(&cfg, broadcast_kernel, out);
    }
}